// round 8
// baseline (speedup 1.0000x reference)
#include <cuda_runtime.h>
#include <cuda_bf16.h>
#include <cstdint>

#define NN 50000
#define NE 800000
#define DD 128
#define KK 256

// tcgen05 only exists in the arch-specific (sm_103a) target. The generic pass
// gets the R7-proven mma.sync HMMA implementation, so whichever cubin the
// loader selects is correct; the TC cubin is the fast path.
#if defined(__CUDA_ARCH__) && (defined(__CUDA_ARCH_FEAT_SM103_ALL) || defined(__CUDA_ARCH_SPECIFIC__) || defined(__CUDA_ARCH_FAMILY_SPECIFIC__))
#define HAS_TC 1
#else
#define HAS_TC 0
#endif

// ---------------- scratch ----------------------------------------------------
__device__ float g_ef1[(size_t)NE * DD];     // ef @ W_edge
__device__ float g_s[(size_t)NN * DD];       // segment sum -> nb
__device__ float g_deg[NN];
// split+transposed weights: B[n][k] = W[k][n], bf16 hi/lo
__device__ __nv_bfloat16 g_Bn_h[DD * DD], g_Bn_l[DD * DD];
__device__ __nv_bfloat16 g_Be_h[DD * DD], g_Be_l[DD * DD];
__device__ __nv_bfloat16 g_Bd_h[DD * KK], g_Bd_l[DD * KK];

// one dynamic-smem size that covers both branches
#define SMEM_BYTES 139264

// ---------------- shared helpers ----------------------------------------------
__device__ __forceinline__ uint32_t smem_u32(const void* p) {
    uint32_t a;
    asm("{ .reg .u64 t; cvta.to.shared.u64 t, %1; cvt.u32.u64 %0, t; }" : "=r"(a) : "l"(p));
    return a;
}

__device__ __forceinline__ void split2(float x, float y, uint32_t& hi, uint32_t& lo) {
    __nv_bfloat162 h = __floats2bfloat162_rn(x, y);
    hi = *(uint32_t*)&h;
    float rx = x - __bfloat162float(__low2bfloat16(h));
    float ry = y - __bfloat162float(__high2bfloat16(h));
    __nv_bfloat162 l = __floats2bfloat162_rn(rx, ry);
    lo = *(uint32_t*)&l;
}

// ---------------- small utility kernels --------------------------------------
__global__ void zero_kernel() {
    int stride = gridDim.x * blockDim.x;
    int t = blockIdx.x * blockDim.x + threadIdx.x;
    for (int i = t; i < NN * DD; i += stride) g_s[i] = 0.0f;
    for (int i = t; i < NN; i += stride) g_deg[i] = 0.0f;
}
__global__ void deg_kernel(const int* __restrict__ dst) {
    int e = blockIdx.x * blockDim.x + threadIdx.x;
    if (e < NE) atomicAdd(&g_deg[dst[e]], 1.0f);
}
__global__ void nb_kernel() {
    int stride = gridDim.x * blockDim.x;
    int t = blockIdx.x * blockDim.x + threadIdx.x;
    for (int i = t; i < NN * DD; i += stride) {
        float d = g_deg[i >> 7];
        g_s[i] = g_s[i] / fmaxf(d, 1.0f);
    }
}

// transpose + bf16-split weights. Destination __device__ globals referenced
// DIRECTLY in device code (passing device symbols as host-side kernel args
// silently writes the host ATS shadow on GB300 — the R3-R6 bug).
__device__ __forceinline__ void split_one(const float* W, int K, int idx,
                                          __nv_bfloat16* Bh, __nv_bfloat16* Bl) {
    int n = idx / K, k = idx % K;
    float v = W[(size_t)k * 128 + n];
    __nv_bfloat16 h = __float2bfloat16(v);
    Bh[idx] = h;
    Bl[idx] = __float2bfloat16(v - __bfloat162float(h));
}
__global__ void split_w_node(const float* __restrict__ W) {
    int idx = blockIdx.x * blockDim.x + threadIdx.x;
    if (idx < 128 * 128) split_one(W, 128, idx, g_Bn_h, g_Bn_l);
}
__global__ void split_w_edge(const float* __restrict__ W) {
    int idx = blockIdx.x * blockDim.x + threadIdx.x;
    if (idx < 128 * 128) split_one(W, 128, idx, g_Be_h, g_Be_l);
}
__global__ void split_w_dense(const float* __restrict__ W) {
    int idx = blockIdx.x * blockDim.x + threadIdx.x;
    if (idx < 128 * 256) split_one(W, 256, idx, g_Bd_h, g_Bd_l);
}

#if HAS_TC
// =========================== tcgen05 fast path =============================
__device__ __forceinline__ uint32_t elect_one() {
    uint32_t p;
    asm volatile("{ .reg .pred p; elect.sync _|p, 0xFFFFFFFF; selp.b32 %0, 1, 0, p; }" : "=r"(p));
    return p;
}
#define TC_ALLOC(addr, n)   asm volatile("tcgen05.alloc.cta_group::1.sync.aligned.shared::cta.b32 [%0], %1;" :: "r"(addr), "r"(n) : "memory")
#define TC_DEALLOC(t, n)    asm volatile("tcgen05.dealloc.cta_group::1.sync.aligned.b32 %0, %1;" :: "r"(t), "r"(n))
#define TC_COMMIT(mb)       asm volatile("tcgen05.commit.cta_group::1.mbarrier::arrive::one.shared::cluster.b64 [%0];" :: "r"(mb) : "memory")
#define TC_WAIT_LD()        asm volatile("tcgen05.wait::ld.sync.aligned;" ::: "memory")
#define TC_WAIT_ST()        asm volatile("tcgen05.wait::st.sync.aligned;" ::: "memory")
#define TC_FENCE_AFTER()    asm volatile("tcgen05.fence::after_thread_sync;" ::: "memory")
#define TC_FENCE_BEFORE()   asm volatile("tcgen05.fence::before_thread_sync;" ::: "memory")
#define FENCE_ASYNC_SHARED() asm volatile("fence.proxy.async.shared::cta;" ::: "memory")
#define MBAR_INIT(mb, cnt)  asm volatile("mbarrier.init.shared.b64 [%0], %1;" :: "r"(mb), "r"(cnt) : "memory")
#define MBAR_INVAL(mb)      asm volatile("mbarrier.inval.shared.b64 [%0];" :: "r"(mb) : "memory")

__device__ __forceinline__ void mbar_wait(uint32_t mb, uint32_t parity) {
    uint32_t done;
    asm volatile(
        "{ .reg .pred p; mbarrier.try_wait.parity.acquire.cta.shared::cta.b64 p, [%1], %2; selp.b32 %0, 1, 0, p; }"
        : "=r"(done) : "r"(mb), "r"(parity) : "memory");
    if (!done) {
        asm volatile(
            "{ .reg .pred P1;\n"
            "WL_%=: mbarrier.try_wait.parity.acquire.cta.shared::cta.b64 P1, [%0], %1, 0x989680;\n"
            "@P1 bra.uni WD_%=;\n bra.uni WL_%=;\n WD_%=: }"
            :: "r"(mb), "r"(parity) : "memory");
    }
}

#define TC_LD_X32(r, t) \
    asm volatile("tcgen05.ld.sync.aligned.32x32b.x32.b32 " \
        "{%0,%1,%2,%3,%4,%5,%6,%7,%8,%9,%10,%11,%12,%13,%14,%15," \
        "%16,%17,%18,%19,%20,%21,%22,%23,%24,%25,%26,%27,%28,%29,%30,%31}, [%32];" \
        : "=r"((r)[0]),"=r"((r)[1]),"=r"((r)[2]),"=r"((r)[3]),"=r"((r)[4]),"=r"((r)[5]),"=r"((r)[6]),"=r"((r)[7]), \
          "=r"((r)[8]),"=r"((r)[9]),"=r"((r)[10]),"=r"((r)[11]),"=r"((r)[12]),"=r"((r)[13]),"=r"((r)[14]),"=r"((r)[15]), \
          "=r"((r)[16]),"=r"((r)[17]),"=r"((r)[18]),"=r"((r)[19]),"=r"((r)[20]),"=r"((r)[21]),"=r"((r)[22]),"=r"((r)[23]), \
          "=r"((r)[24]),"=r"((r)[25]),"=r"((r)[26]),"=r"((r)[27]),"=r"((r)[28]),"=r"((r)[29]),"=r"((r)[30]),"=r"((r)[31]) \
        : "r"(t))

#define TC_ST_X32(t, r) \
    asm volatile("tcgen05.st.sync.aligned.32x32b.x32.b32 [%0], " \
        "{%1,%2,%3,%4,%5,%6,%7,%8,%9,%10,%11,%12,%13,%14,%15,%16," \
        "%17,%18,%19,%20,%21,%22,%23,%24,%25,%26,%27,%28,%29,%30,%31,%32};" \
        :: "r"(t), \
           "r"((r)[0]),"r"((r)[1]),"r"((r)[2]),"r"((r)[3]),"r"((r)[4]),"r"((r)[5]),"r"((r)[6]),"r"((r)[7]), \
           "r"((r)[8]),"r"((r)[9]),"r"((r)[10]),"r"((r)[11]),"r"((r)[12]),"r"((r)[13]),"r"((r)[14]),"r"((r)[15]), \
           "r"((r)[16]),"r"((r)[17]),"r"((r)[18]),"r"((r)[19]),"r"((r)[20]),"r"((r)[21]),"r"((r)[22]),"r"((r)[23]), \
           "r"((r)[24]),"r"((r)[25]),"r"((r)[26]),"r"((r)[27]),"r"((r)[28]),"r"((r)[29]),"r"((r)[30]),"r"((r)[31]) \
        : "memory")

// SW128 smem descriptor (validated): layout=SW128, version=1, SBO=64, LBO=1
static constexpr uint64_t DESC_BASE =
    (uint64_t(2) << 61) | (uint64_t(1) << 46) | (uint64_t(64) << 32) | (uint64_t(1) << 16);
__device__ __forceinline__ uint64_t mk_desc(uint32_t addr) {
    return DESC_BASE | ((uint64_t)(addr >> 4) & 0x3FFF);
}

// idesc literal from validated test_mma/test_mma_iter: F32, bf16/bf16, M=128, N=32
static constexpr uint32_t IDESC32 = 0x8080490u;

__device__ __forceinline__ void mma_f16_ts(uint32_t d, uint32_t a_tmem,
                                           uint64_t b_desc, uint32_t en) {
    asm volatile(
        "{ .reg .pred p; setp.ne.u32 p, %5, 0;\n"
        "tcgen05.mma.cta_group::1.kind::f16 [%0], [%1], %2, %3, {%4, %4, %4, %4}, p; }"
        :: "r"(d), "r"(a_tmem), "l"(b_desc), "r"(IDESC32), "r"(0u), "r"(en) : "memory");
}

// One N=32 chunk, K=128, 3 bf16-splits. Descriptor offsets {0,2,4,6,256,...}
// and A tmem offsets m*8 are the validated MMA_DESC_OFFSETS pattern.
__device__ __forceinline__ void mma_rs_chain(uint32_t d, uint32_t ah, uint32_t al,
                                             uint64_t bh, uint64_t bl, bool first) {
    uint32_t as[3] = {ah, ah, al};
    uint64_t bs[3] = {bh, bl, bh};
#pragma unroll
    for (int s = 0; s < 3; s++) {
#pragma unroll
        for (int m = 0; m < 8; m++) {
            uint64_t boff = (uint64_t)((m & 3) * 2 + (m >> 2) * 256);
            uint32_t en = (first && s == 0 && m == 0) ? 0u : 1u;
            mma_f16_ts(d, as[s] + m * 8, bs[s] + boff, en);
        }
    }
}

// B tile: 32 rows x 128 cols bf16, blocked atoms exactly as test_mma_iter:
// atom = 8 rows x 64 cols (1024B), atom_offset = (r>>3) + (c>>6)*4
__device__ __forceinline__ uint32_t btile_off(int r, int c) {
    uint32_t b = (uint32_t)(((r >> 3) + ((c >> 6) << 2)) * 1024 + (r & 7) * 128 + (c & 63) * 2);
    return b ^ ((b >> 3) & 0x70);
}

// pack 64 fp32 into 32 bf16x2 hi + 32 lo; store to TMEM (validated A packing)
__device__ __forceinline__ void st_a_half(uint32_t ah, uint32_t al, const float4* v) {
    uint32_t hi[32], lo[32];
#pragma unroll
    for (int i = 0; i < 16; i++) {
        split2(v[i].x, v[i].y, hi[2 * i], lo[2 * i]);
        split2(v[i].z, v[i].w, hi[2 * i + 1], lo[2 * i + 1]);
    }
    TC_ST_X32(ah, hi);
    TC_ST_X32(al, lo);
}

// fill 4 N-chunk B tile pairs (hi+lo) for one K=128 block of weights.
__device__ __forceinline__ void fill_B_tiles(char* smem, int dstBase,
                                             const __nv_bfloat16* bh,
                                             const __nv_bfloat16* bl,
                                             int strideElems, int kOff, int tid) {
#pragma unroll
    for (int i = 0; i < 8; i++) {
        int idx = tid + i * 256;
        int n = idx >> 4, c16 = idx & 15;
        int nc = n >> 5, r = n & 31;
        uint32_t off = btile_off(r, c16 * 8);
        char* base = smem + dstBase + nc * 16384;
        *(uint4*)(base + off)        = ((const uint4*)(bh + (size_t)n * strideElems + kOff))[c16];
        *(uint4*)(base + 8192 + off) = ((const uint4*)(bl + (size_t)n * strideElems + kOff))[c16];
    }
}

// TMEM col map: D 0..127 (4 x N=32), A0h 128, A0l 192, A1h 256, A1l 320
static constexpr int TD = 0, TA0H = 128, TA0L = 192, TA1H = 256, TA1L = 320;
#endif  // HAS_TC

#if !HAS_TC
// ============================ HMMA fallback (R7) ============================
#define WPAD 68
#define SA_H 0
#define SA_L (128 * WPAD)
#define SB_H (2 * 128 * WPAD)
#define SB_L (3 * 128 * WPAD)

__device__ __forceinline__ void mma_bf16(float* d, const uint32_t* a,
                                         uint32_t b0, uint32_t b1) {
    asm volatile(
        "mma.sync.aligned.m16n8k16.row.col.f32.bf16.bf16.f32 "
        "{%0,%1,%2,%3}, {%4,%5,%6,%7}, {%8,%9}, {%0,%1,%2,%3};"
        : "+f"(d[0]), "+f"(d[1]), "+f"(d[2]), "+f"(d[3])
        : "r"(a[0]), "r"(a[1]), "r"(a[2]), "r"(a[3]), "r"(b0), "r"(b1));
}

__device__ __forceinline__ void fillB(uint32_t* sm, const __nv_bfloat16* bh,
                                      const __nv_bfloat16* bl, int strideElems,
                                      int kOff, int tid) {
#pragma unroll
    for (int i = 0; i < 32; i++) {
        int idx = tid + i * 256;
        int n = idx >> 6, w = idx & 63;
        sm[SB_H + n * WPAD + w] = *(const uint32_t*)(bh + (size_t)n * strideElems + kOff + 2 * w);
        sm[SB_L + n * WPAD + w] = *(const uint32_t*)(bl + (size_t)n * strideElems + kOff + 2 * w);
    }
}

__device__ __forceinline__ void kloop(const uint32_t* sm, int lane, int mbase,
                                      int nbase, float acc[2][8][4]) {
    const int g = lane >> 2, t = lane & 3;
#pragma unroll
    for (int ks = 0; ks < 8; ks++) {
        const int kw = ks * 8 + t;
        uint32_t ah[2][4], al[2][4];
#pragma unroll
        for (int mt = 0; mt < 2; mt++) {
            int r = mbase + mt * 16 + g;
            ah[mt][0] = sm[SA_H + r * WPAD + kw];
            ah[mt][1] = sm[SA_H + (r + 8) * WPAD + kw];
            ah[mt][2] = sm[SA_H + r * WPAD + kw + 4];
            ah[mt][3] = sm[SA_H + (r + 8) * WPAD + kw + 4];
            al[mt][0] = sm[SA_L + r * WPAD + kw];
            al[mt][1] = sm[SA_L + (r + 8) * WPAD + kw];
            al[mt][2] = sm[SA_L + r * WPAD + kw + 4];
            al[mt][3] = sm[SA_L + (r + 8) * WPAD + kw + 4];
        }
#pragma unroll
        for (int j = 0; j < 8; j++) {
            int n = nbase + j * 8 + g;
            uint32_t bh0 = sm[SB_H + n * WPAD + kw];
            uint32_t bh1 = sm[SB_H + n * WPAD + kw + 4];
            uint32_t bl0 = sm[SB_L + n * WPAD + kw];
            uint32_t bl1 = sm[SB_L + n * WPAD + kw + 4];
#pragma unroll
            for (int mt = 0; mt < 2; mt++) {
                mma_bf16(acc[mt][j], ah[mt], bh0, bh1);
                mma_bf16(acc[mt][j], ah[mt], bl0, bl1);
                mma_bf16(acc[mt][j], al[mt], bh0, bh1);
            }
        }
    }
}
#endif  // !HAS_TC

// ---------------- GEMM kernels ------------------------------------------------

__global__ __launch_bounds__(256, 1)
void node_gemm(const float* __restrict__ nf, const float* __restrict__ bias,
               float* __restrict__ out) {
#if HAS_TC
    extern __shared__ __align__(1024) char smem_raw[];
    __shared__ uint32_t s_tmem;
    __shared__ __align__(8) uint64_t s_mbar;
    char* smem = (char*)(((uintptr_t)smem_raw + 1023) & ~(uintptr_t)1023);
    uint32_t mb = smem_u32(&s_mbar);
    const int tid = threadIdx.x, wid = tid >> 5, lane = tid & 31;
    const int r0 = blockIdx.x * 128;

    if (wid == 0) TC_ALLOC(smem_u32(&s_tmem), 256);
    if (tid == 0) MBAR_INIT(mb, 1);
    __syncthreads();
    uint32_t tmem = s_tmem;
    uint32_t sb = smem_u32(smem);

    fill_B_tiles(smem, 0, g_Bn_h, g_Bn_l, 128, 0, tid);

    if (tid < 128) {
        uint32_t woff = (uint32_t)(tid >> 5) << 21;
        int row = r0 + tid;
        const float4* src = (const float4*)(nf + (size_t)row * DD);
#pragma unroll
        for (int h = 0; h < 2; h++) {
            float4 v[16];
#pragma unroll
            for (int i = 0; i < 16; i++)
                v[i] = (row < NN) ? src[h * 16 + i] : make_float4(0.f, 0.f, 0.f, 0.f);
            st_a_half(tmem + TA0H + woff + h * 32, tmem + TA0L + woff + h * 32, v);
        }
        TC_WAIT_ST();
    }
    FENCE_ASYNC_SHARED();
    __syncthreads();

    if (wid == 0 && elect_one()) {
#pragma unroll
        for (int nc = 0; nc < 4; nc++) {
            uint64_t bh = mk_desc(sb + nc * 16384);
            uint64_t bl = mk_desc(sb + nc * 16384 + 8192);
            mma_rs_chain(tmem + TD + nc * 32, tmem + TA0H, tmem + TA0L, bh, bl, true);
        }
        TC_COMMIT(mb);
    }
    mbar_wait(mb, 0);
    TC_FENCE_AFTER();

    int row = 32 * (wid & 3) + lane;
    int grow = r0 + row;
    int cbase = (wid >> 2) * 64;
#pragma unroll
    for (int ch = 0; ch < 2; ch++) {
        uint32_t regs[32];
        TC_LD_X32(regs, tmem + TD + cbase + ch * 32);
        TC_WAIT_LD();
        TC_FENCE_BEFORE();
        if (grow < NN) {
            float* op = out + (size_t)grow * DD + cbase + ch * 32;
            const float* bp = bias + cbase + ch * 32;
#pragma unroll
            for (int j = 0; j < 32; j += 4) {
                float4 o;
                o.x = fmaxf(__uint_as_float(regs[j + 0]) + bp[j + 0], 0.f);
                o.y = fmaxf(__uint_as_float(regs[j + 1]) + bp[j + 1], 0.f);
                o.z = fmaxf(__uint_as_float(regs[j + 2]) + bp[j + 2], 0.f);
                o.w = fmaxf(__uint_as_float(regs[j + 3]) + bp[j + 3], 0.f);
                *(float4*)(op + j) = o;
            }
        }
    }
    __syncthreads();
    if (tid == 0) MBAR_INVAL(mb);
    if (wid == 0) TC_DEALLOC(tmem, 256);
#else
    extern __shared__ uint32_t sm[];
    const int tid = threadIdx.x, lane = tid & 31, wid = tid >> 5;
    const int rowbase = blockIdx.x * 128;

    fillB(sm, g_Bn_h, g_Bn_l, 128, 0, tid);
#pragma unroll
    for (int i = 0; i < 32; i++) {
        int idx = tid + i * 256;
        int r = idx >> 6, w = idx & 63;
        int row = rowbase + r;
        float2 v = make_float2(0.f, 0.f);
        if (row < NN) v = *(const float2*)(nf + (size_t)row * DD + 2 * w);
        split2(v.x, v.y, sm[SA_H + r * WPAD + w], sm[SA_L + r * WPAD + w]);
    }
    __syncthreads();

    const int mbase = (wid & 3) * 32, nbase = (wid >> 2) * 64;
    float acc[2][8][4];
#pragma unroll
    for (int a = 0; a < 2; a++)
#pragma unroll
        for (int b = 0; b < 8; b++)
#pragma unroll
            for (int c = 0; c < 4; c++) acc[a][b][c] = 0.f;
    kloop(sm, lane, mbase, nbase, acc);

    const int g = lane >> 2, t = lane & 3;
#pragma unroll
    for (int mt = 0; mt < 2; mt++) {
        int row = rowbase + mbase + mt * 16 + g;
#pragma unroll
        for (int j = 0; j < 8; j++) {
            int c = nbase + j * 8 + 2 * t;
            float2 bv = *(const float2*)(bias + c);
            if (row < NN) {
                float2 o = make_float2(fmaxf(acc[mt][j][0] + bv.x, 0.f),
                                       fmaxf(acc[mt][j][1] + bv.y, 0.f));
                *(float2*)(out + (size_t)row * DD + c) = o;
            }
            if (row + 8 < NN) {
                float2 o = make_float2(fmaxf(acc[mt][j][2] + bv.x, 0.f),
                                       fmaxf(acc[mt][j][3] + bv.y, 0.f));
                *(float2*)(out + (size_t)(row + 8) * DD + c) = o;
            }
        }
    }
#endif
}

__global__ __launch_bounds__(256, 1)
void edge_gemm(const float* __restrict__ ef, const int* __restrict__ dst) {
#if HAS_TC
    extern __shared__ __align__(1024) char smem_raw[];
    __shared__ uint32_t s_tmem;
    __shared__ __align__(8) uint64_t s_mbar;
    char* smem = (char*)(((uintptr_t)smem_raw + 1023) & ~(uintptr_t)1023);
    uint32_t mb = smem_u32(&s_mbar);
    const int tid = threadIdx.x, wid = tid >> 5, lane = tid & 31;
    const int e0 = blockIdx.x * 128;

    if (wid == 0) TC_ALLOC(smem_u32(&s_tmem), 256);
    if (tid == 0) MBAR_INIT(mb, 1);
    __syncthreads();
    uint32_t tmem = s_tmem;
    uint32_t sb = smem_u32(smem);

    fill_B_tiles(smem, 0, g_Be_h, g_Be_l, 128, 0, tid);

    if (tid < 128) {
        uint32_t woff = (uint32_t)(tid >> 5) << 21;
        const float4* src = (const float4*)(ef + (size_t)(e0 + tid) * DD);
#pragma unroll
        for (int h = 0; h < 2; h++) {
            float4 v[16];
#pragma unroll
            for (int i = 0; i < 16; i++) v[i] = src[h * 16 + i];
            st_a_half(tmem + TA0H + woff + h * 32, tmem + TA0L + woff + h * 32, v);
        }
        TC_WAIT_ST();
    }
    FENCE_ASYNC_SHARED();
    __syncthreads();

    if (wid == 0 && elect_one()) {
#pragma unroll
        for (int nc = 0; nc < 4; nc++) {
            uint64_t bh = mk_desc(sb + nc * 16384);
            uint64_t bl = mk_desc(sb + nc * 16384 + 8192);
            mma_rs_chain(tmem + TD + nc * 32, tmem + TA0H, tmem + TA0L, bh, bl, true);
        }
        TC_COMMIT(mb);
    }
    mbar_wait(mb, 0);
    TC_FENCE_AFTER();

    int row = 32 * (wid & 3) + lane;
    int e = e0 + row;
    int dn = dst[e];
    int cbase = (wid >> 2) * 64;
#pragma unroll
    for (int ch = 0; ch < 2; ch++) {
        uint32_t regs[32];
        TC_LD_X32(regs, tmem + TD + cbase + ch * 32);
        TC_WAIT_LD();
        TC_FENCE_BEFORE();
        float* op = g_ef1 + (size_t)e * DD + cbase + ch * 32;
        float* sp = g_s + (size_t)dn * DD + cbase + ch * 32;
#pragma unroll
        for (int j = 0; j < 32; j += 4) {
            float4 o = make_float4(__uint_as_float(regs[j]), __uint_as_float(regs[j + 1]),
                                   __uint_as_float(regs[j + 2]), __uint_as_float(regs[j + 3]));
            *(float4*)(op + j) = o;
        }
#pragma unroll
        for (int j = 0; j < 32; j++) atomicAdd(sp + j, __uint_as_float(regs[j]));
    }
    __syncthreads();
    if (tid == 0) MBAR_INVAL(mb);
    if (wid == 0) TC_DEALLOC(tmem, 256);
#else
    extern __shared__ uint32_t sm[];
    const int tid = threadIdx.x, lane = tid & 31, wid = tid >> 5;
    const int e0 = blockIdx.x * 128;

    fillB(sm, g_Be_h, g_Be_l, 128, 0, tid);
#pragma unroll
    for (int i = 0; i < 32; i++) {
        int idx = tid + i * 256;
        int r = idx >> 6, w = idx & 63;
        float2 v = *(const float2*)(ef + (size_t)(e0 + r) * DD + 2 * w);
        split2(v.x, v.y, sm[SA_H + r * WPAD + w], sm[SA_L + r * WPAD + w]);
    }
    __syncthreads();

    const int mbase = (wid & 3) * 32, nbase = (wid >> 2) * 64;
    float acc[2][8][4];
#pragma unroll
    for (int a = 0; a < 2; a++)
#pragma unroll
        for (int b = 0; b < 8; b++)
#pragma unroll
            for (int c = 0; c < 4; c++) acc[a][b][c] = 0.f;
    kloop(sm, lane, mbase, nbase, acc);

    const int g = lane >> 2, t = lane & 3;
#pragma unroll
    for (int mt = 0; mt < 2; mt++) {
        int e = e0 + mbase + mt * 16 + g;
        int dn0 = dst[e], dn1 = dst[e + 8];
#pragma unroll
        for (int j = 0; j < 8; j++) {
            int c = nbase + j * 8 + 2 * t;
            float d0 = acc[mt][j][0], d1 = acc[mt][j][1];
            float d2 = acc[mt][j][2], d3 = acc[mt][j][3];
            *(float2*)(g_ef1 + (size_t)e * DD + c) = make_float2(d0, d1);
            *(float2*)(g_ef1 + (size_t)(e + 8) * DD + c) = make_float2(d2, d3);
            atomicAdd(g_s + (size_t)dn0 * DD + c, d0);
            atomicAdd(g_s + (size_t)dn0 * DD + c + 1, d1);
            atomicAdd(g_s + (size_t)dn1 * DD + c, d2);
            atomicAdd(g_s + (size_t)dn1 * DD + c + 1, d3);
        }
    }
#endif
}

__global__ __launch_bounds__(256, 1)
void edge_out_gemm(const int* __restrict__ src, const int* __restrict__ dst,
                   const float* __restrict__ db, const float* __restrict__ eb,
                   const float* __restrict__ nf2, float* __restrict__ out) {
#if HAS_TC
    extern __shared__ __align__(1024) char smem_raw[];
    __shared__ uint32_t s_tmem;
    __shared__ __align__(8) uint64_t s_mbar;
    char* smem = (char*)(((uintptr_t)smem_raw + 1023) & ~(uintptr_t)1023);
    uint32_t mb = smem_u32(&s_mbar);
    const int tid = threadIdx.x, wid = tid >> 5, lane = tid & 31;
    const int e0 = blockIdx.x * 128;

    if (wid == 0) TC_ALLOC(smem_u32(&s_tmem), 512);
    if (tid == 0) MBAR_INIT(mb, 1);
    __syncthreads();
    uint32_t tmem = s_tmem;
    uint32_t sb = smem_u32(smem);

    // B for both K-chunks: chunk kc at kc*65536
    fill_B_tiles(smem, 0,     g_Bd_h, g_Bd_l, KK, 0,   tid);
    fill_B_tiles(smem, 65536, g_Bd_h, g_Bd_l, KK, 128, tid);

    if (tid < 128) {
        uint32_t woff = (uint32_t)(tid >> 5) << 21;
        int e = e0 + tid;
        int dn = dst[e], sn = src[e];
        const float4* pe = (const float4*)(g_ef1 + (size_t)e * DD);
        const float4* ps = (const float4*)(g_s + (size_t)dn * DD);
        const float4* p1 = (const float4*)(nf2 + (size_t)sn * DD);
        const float4* p2 = (const float4*)(nf2 + (size_t)dn * DD);
#pragma unroll
        for (int h = 0; h < 2; h++) {
            float4 v[16];
#pragma unroll
            for (int i = 0; i < 16; i++) {
                float4 a = pe[h * 16 + i], b = ps[h * 16 + i];
                v[i] = make_float4(a.x + b.x, a.y + b.y, a.z + b.z, a.w + b.w);
            }
            st_a_half(tmem + TA0H + woff + h * 32, tmem + TA0L + woff + h * 32, v);
#pragma unroll
            for (int i = 0; i < 16; i++) {
                float4 a = p1[h * 16 + i], b = p2[h * 16 + i];
                v[i] = make_float4(0.5f * (a.x + b.x), 0.5f * (a.y + b.y),
                                   0.5f * (a.z + b.z), 0.5f * (a.w + b.w));
            }
            st_a_half(tmem + TA1H + woff + h * 32, tmem + TA1L + woff + h * 32, v);
        }
        TC_WAIT_ST();
    }
    FENCE_ASYNC_SHARED();
    __syncthreads();

    if (wid == 0 && elect_one()) {
#pragma unroll
        for (int nc = 0; nc < 4; nc++) {
            uint32_t d = tmem + TD + nc * 32;
            uint64_t bh0 = mk_desc(sb + nc * 16384);
            uint64_t bl0 = mk_desc(sb + nc * 16384 + 8192);
            uint64_t bh1 = mk_desc(sb + 65536 + nc * 16384);
            uint64_t bl1 = mk_desc(sb + 65536 + nc * 16384 + 8192);
            mma_rs_chain(d, tmem + TA0H, tmem + TA0L, bh0, bl0, true);
            mma_rs_chain(d, tmem + TA1H, tmem + TA1L, bh1, bl1, false);
        }
        TC_COMMIT(mb);
    }
    mbar_wait(mb, 0);
    TC_FENCE_AFTER();

    int row = 32 * (wid & 3) + lane;
    int e = e0 + row;
    int cbase = (wid >> 2) * 64;
#pragma unroll
    for (int ch = 0; ch < 2; ch++) {
        uint32_t regs[32];
        TC_LD_X32(regs, tmem + TD + cbase + ch * 32);
        TC_WAIT_LD();
        TC_FENCE_BEFORE();
        float* op = out + (size_t)e * DD + cbase + ch * 32;
        const float* b1 = db + cbase + ch * 32;
        const float* b2 = eb + cbase + ch * 32;
#pragma unroll
        for (int j = 0; j < 32; j += 4) {
            float4 o;
            o.x = fmaxf(__uint_as_float(regs[j + 0]) + b1[j + 0] + b2[j + 0], 0.f);
            o.y = fmaxf(__uint_as_float(regs[j + 1]) + b1[j + 1] + b2[j + 1], 0.f);
            o.z = fmaxf(__uint_as_float(regs[j + 2]) + b1[j + 2] + b2[j + 2], 0.f);
            o.w = fmaxf(__uint_as_float(regs[j + 3]) + b1[j + 3] + b2[j + 3], 0.f);
            *(float4*)(op + j) = o;
        }
    }
    __syncthreads();
    if (tid == 0) MBAR_INVAL(mb);
    if (wid == 0) TC_DEALLOC(tmem, 512);
#else
    extern __shared__ uint32_t sm[];
    const int tid = threadIdx.x, lane = tid & 31, wid = tid >> 5;
    const int e0 = blockIdx.x * 128;
    const int mbase = (wid & 3) * 32, nbase = (wid >> 2) * 64;

    float acc[2][8][4];
#pragma unroll
    for (int a = 0; a < 2; a++)
#pragma unroll
        for (int b = 0; b < 8; b++)
#pragma unroll
            for (int c = 0; c < 4; c++) acc[a][b][c] = 0.f;

    fillB(sm, g_Bd_h, g_Bd_l, KK, 0, tid);
#pragma unroll
    for (int i = 0; i < 32; i++) {
        int idx = tid + i * 256;
        int r = idx >> 6, w = idx & 63;
        int e = e0 + r;
        int dn = dst[e];
        float2 a = *(const float2*)(g_ef1 + (size_t)e * DD + 2 * w);
        float2 b = *(const float2*)(g_s + (size_t)dn * DD + 2 * w);
        split2(a.x + b.x, a.y + b.y, sm[SA_H + r * WPAD + w], sm[SA_L + r * WPAD + w]);
    }
    __syncthreads();
    kloop(sm, lane, mbase, nbase, acc);
    __syncthreads();

    fillB(sm, g_Bd_h, g_Bd_l, KK, 128, tid);
#pragma unroll
    for (int i = 0; i < 32; i++) {
        int idx = tid + i * 256;
        int r = idx >> 6, w = idx & 63;
        int e = e0 + r;
        int sn = src[e], dn = dst[e];
        float2 a = *(const float2*)(nf2 + (size_t)sn * DD + 2 * w);
        float2 b = *(const float2*)(nf2 + (size_t)dn * DD + 2 * w);
        split2(0.5f * (a.x + b.x), 0.5f * (a.y + b.y),
               sm[SA_H + r * WPAD + w], sm[SA_L + r * WPAD + w]);
    }
    __syncthreads();
    kloop(sm, lane, mbase, nbase, acc);

    const int g = lane >> 2, t = lane & 3;
#pragma unroll
    for (int mt = 0; mt < 2; mt++) {
        int e = e0 + mbase + mt * 16 + g;
#pragma unroll
        for (int j = 0; j < 8; j++) {
            int c = nbase + j * 8 + 2 * t;
            float2 b1 = *(const float2*)(db + c);
            float2 b2 = *(const float2*)(eb + c);
            float2 o0 = make_float2(fmaxf(acc[mt][j][0] + b1.x + b2.x, 0.f),
                                    fmaxf(acc[mt][j][1] + b1.y + b2.y, 0.f));
            float2 o1 = make_float2(fmaxf(acc[mt][j][2] + b1.x + b2.x, 0.f),
                                    fmaxf(acc[mt][j][3] + b1.y + b2.y, 0.f));
            *(float2*)(out + (size_t)e * DD + c) = o0;
            *(float2*)(out + (size_t)(e + 8) * DD + c) = o1;
        }
    }
#endif
}

// ---------------- launch ------------------------------------------------------
extern "C" void kernel_launch(void* const* d_in, const int* in_sizes, int n_in,
                              void* d_out, int out_size) {
    (void)in_sizes; (void)n_in; (void)out_size;
    const float* nf        = (const float*)d_in[0];
    const float* ef        = (const float*)d_in[1];
    const float* W_node    = (const float*)d_in[2];
    const float* W_edge    = (const float*)d_in[3];
    const float* node_bias = (const float*)d_in[4];
    const float* edge_bias = (const float*)d_in[5];
    const float* dense_W   = (const float*)d_in[6];
    const float* dense_b   = (const float*)d_in[7];
    const int*   src       = (const int*)d_in[8];
    const int*   dst       = (const int*)d_in[9];

    float* nf2 = (float*)d_out;
    float* ef2 = (float*)d_out + (size_t)NN * DD;

    cudaFuncSetAttribute(node_gemm, cudaFuncAttributeMaxDynamicSharedMemorySize, SMEM_BYTES);
    cudaFuncSetAttribute(edge_gemm, cudaFuncAttributeMaxDynamicSharedMemorySize, SMEM_BYTES);
    cudaFuncSetAttribute(edge_out_gemm, cudaFuncAttributeMaxDynamicSharedMemorySize, SMEM_BYTES);

    zero_kernel<<<1024, 256>>>();
    deg_kernel<<<(NE + 255) / 256, 256>>>(dst);
    split_w_node<<<(128 * 128 + 255) / 256, 256>>>(W_node);
    split_w_edge<<<(128 * 128 + 255) / 256, 256>>>(W_edge);
    split_w_dense<<<(128 * 256 + 255) / 256, 256>>>(dense_W);

    node_gemm<<<(NN + 127) / 128, 256, SMEM_BYTES>>>(nf, node_bias, nf2);
    edge_gemm<<<NE / 128, 256, SMEM_BYTES>>>(ef, dst);
    nb_kernel<<<1024, 256>>>();
    edge_out_gemm<<<NE / 128, 256, SMEM_BYTES>>>(src, dst, dense_b, edge_bias, nf2, ef2);
}

// round 9
// speedup vs baseline: 1.6695x; 1.6695x over previous
#include <cuda_runtime.h>
#include <cuda_bf16.h>
#include <cstdint>

#define NN 50000
#define NE 800000
#define DD 128

// ---------------- scratch (device globals; referenced ONLY in device code) ----
__device__ float g_s[(size_t)NN * DD];    // segment_sum(ef, dst)
__device__ float g_deg[NN];
__device__ float g_nb[(size_t)NN * DD];   // (S @ We) / max(deg,1)
__device__ float g_t1[(size_t)NN * DD];   // nb @ Wd1
__device__ float g_t2[(size_t)NN * DD];   // nf2 @ Wd2
__device__ float g_M[DD * DD];            // We @ Wd1 (fp32)
// bf16 hi/lo splits, B layout: B[n][k] = W[k][n]
__device__ __nv_bfloat16 g_Bn_h[DD * DD], g_Bn_l[DD * DD];     // W_node
__device__ __nv_bfloat16 g_Be_h[DD * DD], g_Be_l[DD * DD];     // W_edge
__device__ __nv_bfloat16 g_Bd1_h[DD * DD], g_Bd1_l[DD * DD];   // dense_W[0:128]
__device__ __nv_bfloat16 g_Bd2_h[DD * DD], g_Bd2_l[DD * DD];   // dense_W[128:256]
__device__ __nv_bfloat16 g_Bm_h[DD * DD], g_Bm_l[DD * DD];     // M = We@Wd1

// ---------------- smem layout (32-bit words) ----------------------------------
#define WPAD 68
#define SA_H 0
#define SA_L (128 * WPAD)
#define SB_H (2 * 128 * WPAD)
#define SB_L (3 * 128 * WPAD)
#define SMEM_BYTES (4 * 128 * WPAD * 4)   // 139264

// ---------------- helpers ------------------------------------------------------
__device__ __forceinline__ void split2(float x, float y, uint32_t& hi, uint32_t& lo) {
    __nv_bfloat162 h = __floats2bfloat162_rn(x, y);
    hi = *(uint32_t*)&h;
    float rx = x - __bfloat162float(__low2bfloat16(h));
    float ry = y - __bfloat162float(__high2bfloat16(h));
    __nv_bfloat162 l = __floats2bfloat162_rn(rx, ry);
    lo = *(uint32_t*)&l;
}

__device__ __forceinline__ void mma_bf16(float* d, const uint32_t* a,
                                         uint32_t b0, uint32_t b1) {
    asm volatile(
        "mma.sync.aligned.m16n8k16.row.col.f32.bf16.bf16.f32 "
        "{%0,%1,%2,%3}, {%4,%5,%6,%7}, {%8,%9}, {%0,%1,%2,%3};"
        : "+f"(d[0]), "+f"(d[1]), "+f"(d[2]), "+f"(d[3])
        : "r"(a[0]), "r"(a[1]), "r"(a[2]), "r"(a[3]), "r"(b0), "r"(b1));
}

__device__ __forceinline__ void fillB(uint32_t* sm, const __nv_bfloat16* bh,
                                      const __nv_bfloat16* bl, int tid) {
#pragma unroll
    for (int i = 0; i < 32; i++) {
        int idx = tid + i * 256;
        int n = idx >> 6, w = idx & 63;
        sm[SB_H + n * WPAD + w] = *(const uint32_t*)(bh + (size_t)n * DD + 2 * w);
        sm[SB_L + n * WPAD + w] = *(const uint32_t*)(bl + (size_t)n * DD + 2 * w);
    }
}

// K=128 compute loop: warp computes 32 rows x 64 cols with 3-way bf16 split
__device__ __forceinline__ void kloop(const uint32_t* sm, int lane, int mbase,
                                      int nbase, float acc[2][8][4]) {
    const int g = lane >> 2, t = lane & 3;
#pragma unroll
    for (int ks = 0; ks < 8; ks++) {
        const int kw = ks * 8 + t;
        uint32_t ah[2][4], al[2][4];
#pragma unroll
        for (int mt = 0; mt < 2; mt++) {
            int r = mbase + mt * 16 + g;
            ah[mt][0] = sm[SA_H + r * WPAD + kw];
            ah[mt][1] = sm[SA_H + (r + 8) * WPAD + kw];
            ah[mt][2] = sm[SA_H + r * WPAD + kw + 4];
            ah[mt][3] = sm[SA_H + (r + 8) * WPAD + kw + 4];
            al[mt][0] = sm[SA_L + r * WPAD + kw];
            al[mt][1] = sm[SA_L + (r + 8) * WPAD + kw];
            al[mt][2] = sm[SA_L + r * WPAD + kw + 4];
            al[mt][3] = sm[SA_L + (r + 8) * WPAD + kw + 4];
        }
#pragma unroll
        for (int j = 0; j < 8; j++) {
            int n = nbase + j * 8 + g;
            uint32_t bh0 = sm[SB_H + n * WPAD + kw];
            uint32_t bh1 = sm[SB_H + n * WPAD + kw + 4];
            uint32_t bl0 = sm[SB_L + n * WPAD + kw];
            uint32_t bl1 = sm[SB_L + n * WPAD + kw + 4];
#pragma unroll
            for (int mt = 0; mt < 2; mt++) {
                mma_bf16(acc[mt][j], ah[mt], bh0, bh1);
                mma_bf16(acc[mt][j], ah[mt], bl0, bl1);
                mma_bf16(acc[mt][j], al[mt], bh0, bh1);
            }
        }
    }
}

// ---------------- prep kernels --------------------------------------------------
__global__ void zero_kernel() {
    int stride = gridDim.x * blockDim.x;
    int t = blockIdx.x * blockDim.x + threadIdx.x;
    for (int i = t; i < NN * DD; i += stride) g_s[i] = 0.0f;
    for (int i = t; i < NN; i += stride) g_deg[i] = 0.0f;
}

// scatter raw ef into g_s[dst] + degree count; one warp per edge
__global__ __launch_bounds__(256)
void scatter_ef(const float* __restrict__ ef, const int* __restrict__ dst) {
    int gw = (blockIdx.x * 256 + threadIdx.x) >> 5;   // global warp = edge
    int lane = threadIdx.x & 31;
    if (gw >= NE) return;
    int dn = dst[gw];
    float4 v = ((const float4*)(ef + (size_t)gw * DD))[lane];
    float* sp = g_s + (size_t)dn * DD + lane * 4;
    atomicAdd(sp + 0, v.x);
    atomicAdd(sp + 1, v.y);
    atomicAdd(sp + 2, v.z);
    atomicAdd(sp + 3, v.w);
    if (lane == 0) atomicAdd(&g_deg[dn], 1.0f);
}

// transpose + bf16-split: W is [128,128] row-major (k rows), dest B[n][k]
__device__ __forceinline__ void split_one(const float* W, int idx,
                                          __nv_bfloat16* Bh, __nv_bfloat16* Bl) {
    int n = idx >> 7, k = idx & 127;
    float v = W[(size_t)k * DD + n];
    __nv_bfloat16 h = __float2bfloat16(v);
    Bh[idx] = h;
    Bl[idx] = __float2bfloat16(v - __bfloat162float(h));
}
__global__ void split_w_node(const float* __restrict__ W) {
    int idx = blockIdx.x * blockDim.x + threadIdx.x;
    if (idx < DD * DD) split_one(W, idx, g_Bn_h, g_Bn_l);
}
__global__ void split_w_edge(const float* __restrict__ W) {
    int idx = blockIdx.x * blockDim.x + threadIdx.x;
    if (idx < DD * DD) split_one(W, idx, g_Be_h, g_Be_l);
}
__global__ void split_w_d1(const float* __restrict__ dW) {
    int idx = blockIdx.x * blockDim.x + threadIdx.x;
    if (idx < DD * DD) split_one(dW, idx, g_Bd1_h, g_Bd1_l);
}
__global__ void split_w_d2(const float* __restrict__ dW) {
    int idx = blockIdx.x * blockDim.x + threadIdx.x;
    if (idx < DD * DD) split_one(dW + DD * DD, idx, g_Bd2_h, g_Bd2_l);
}

// M = We @ Wd1 in fp32: M[k][n] = sum_j We[k][j] * dW[j][n]
__global__ void make_M(const float* __restrict__ We, const float* __restrict__ dW) {
    int k = blockIdx.x, n = threadIdx.x;
    float s = 0.f;
#pragma unroll 4
    for (int j = 0; j < DD; j++)
        s = fmaf(We[(size_t)k * DD + j], dW[(size_t)j * DD + n], s);
    g_M[k * DD + n] = s;
}
__global__ void split_M() {
    int idx = blockIdx.x * blockDim.x + threadIdx.x;
    if (idx < DD * DD) split_one(g_M, idx, g_Bm_h, g_Bm_l);
}

// ---------------- node-level GEMMs (mode-dispatched) ---------------------------
// mode 0: nf2  = relu(nf @ Wn + node_bias)        A=Aarg  out=outArg
// mode 1: nb   = (g_s @ We) * 1/max(deg,1)        A=g_s   out=g_nb
// mode 2: t1   = g_nb @ Wd1                        A=g_nb  out=g_t1
// mode 3: t2   = nf2 @ Wd2                         A=Aarg  out=g_t2
__global__ __launch_bounds__(256, 1)
void node_mm(int mode, const float* __restrict__ Aarg,
             const float* __restrict__ bias, float* __restrict__ outArg) {
    extern __shared__ uint32_t sm[];
    const int tid = threadIdx.x, lane = tid & 31, wid = tid >> 5;
    const int rowbase = blockIdx.x * 128;

    const float* A;
    const __nv_bfloat16 *Bh, *Bl;
    float* out;
    if (mode == 0)      { A = Aarg;  Bh = g_Bn_h;  Bl = g_Bn_l;  out = outArg; }
    else if (mode == 1) { A = g_s;   Bh = g_Be_h;  Bl = g_Be_l;  out = g_nb; }
    else if (mode == 2) { A = g_nb;  Bh = g_Bd1_h; Bl = g_Bd1_l; out = g_t1; }
    else                { A = Aarg;  Bh = g_Bd2_h; Bl = g_Bd2_l; out = g_t2; }

    fillB(sm, Bh, Bl, tid);
#pragma unroll
    for (int i = 0; i < 32; i++) {
        int idx = tid + i * 256;
        int r = idx >> 6, w = idx & 63;
        int row = rowbase + r;
        float2 v = make_float2(0.f, 0.f);
        if (row < NN) v = *(const float2*)(A + (size_t)row * DD + 2 * w);
        split2(v.x, v.y, sm[SA_H + r * WPAD + w], sm[SA_L + r * WPAD + w]);
    }
    __syncthreads();

    const int mbase = (wid & 3) * 32, nbase = (wid >> 2) * 64;
    float acc[2][8][4];
#pragma unroll
    for (int a = 0; a < 2; a++)
#pragma unroll
        for (int b = 0; b < 8; b++)
#pragma unroll
            for (int c = 0; c < 4; c++) acc[a][b][c] = 0.f;
    kloop(sm, lane, mbase, nbase, acc);

    const int g = lane >> 2, t = lane & 3;
#pragma unroll
    for (int mt = 0; mt < 2; mt++) {
        int row0 = rowbase + mbase + mt * 16 + g;
        float s0 = 1.f, s1 = 1.f;
        if (mode == 1) {
            if (row0 < NN) s0 = 1.f / fmaxf(g_deg[row0], 1.f);
            if (row0 + 8 < NN) s1 = 1.f / fmaxf(g_deg[row0 + 8], 1.f);
        }
#pragma unroll
        for (int j = 0; j < 8; j++) {
            int c = nbase + j * 8 + 2 * t;
            float2 bv = make_float2(0.f, 0.f);
            if (mode == 0) bv = *(const float2*)(bias + c);
            float o0x = acc[mt][j][0] + bv.x, o0y = acc[mt][j][1] + bv.y;
            float o1x = acc[mt][j][2] + bv.x, o1y = acc[mt][j][3] + bv.y;
            if (mode == 0) {
                o0x = fmaxf(o0x, 0.f); o0y = fmaxf(o0y, 0.f);
                o1x = fmaxf(o1x, 0.f); o1y = fmaxf(o1y, 0.f);
            } else if (mode == 1) {
                o0x *= s0; o0y *= s0; o1x *= s1; o1y *= s1;
            }
            if (row0 < NN)
                *(float2*)(out + (size_t)row0 * DD + c) = make_float2(o0x, o0y);
            if (row0 + 8 < NN)
                *(float2*)(out + (size_t)(row0 + 8) * DD + c) = make_float2(o1x, o1y);
        }
    }
}

// ---------------- fused edge output kernel -------------------------------------
// ef2 = relu(ef @ M + t1[dst] + 0.5*(t2[src]+t2[dst]) + db + eb)
__global__ __launch_bounds__(256, 1)
void edge_out_gemm(const float* __restrict__ ef, const int* __restrict__ src,
                   const int* __restrict__ dst, const float* __restrict__ db,
                   const float* __restrict__ eb, float* __restrict__ out) {
    extern __shared__ uint32_t sm[];
    const int tid = threadIdx.x, lane = tid & 31, wid = tid >> 5;
    const int e0 = blockIdx.x * 128;

    fillB(sm, g_Bm_h, g_Bm_l, tid);
#pragma unroll
    for (int i = 0; i < 32; i++) {
        int idx = tid + i * 256;
        int r = idx >> 6, w = idx & 63;
        float2 v = *(const float2*)(ef + (size_t)(e0 + r) * DD + 2 * w);
        split2(v.x, v.y, sm[SA_H + r * WPAD + w], sm[SA_L + r * WPAD + w]);
    }
    __syncthreads();

    const int mbase = (wid & 3) * 32, nbase = (wid >> 2) * 64;
    float acc[2][8][4];
#pragma unroll
    for (int a = 0; a < 2; a++)
#pragma unroll
        for (int b = 0; b < 8; b++)
#pragma unroll
            for (int c = 0; c < 4; c++) acc[a][b][c] = 0.f;
    kloop(sm, lane, mbase, nbase, acc);

    const int g = lane >> 2, t = lane & 3;
#pragma unroll
    for (int mt = 0; mt < 2; mt++) {
        int e = e0 + mbase + mt * 16 + g;
        int dnA = dst[e], snA = src[e];
        int dnB = dst[e + 8], snB = src[e + 8];
        const float* t1A = g_t1 + (size_t)dnA * DD;
        const float* t2sA = g_t2 + (size_t)snA * DD;
        const float* t2dA = g_t2 + (size_t)dnA * DD;
        const float* t1B = g_t1 + (size_t)dnB * DD;
        const float* t2sB = g_t2 + (size_t)snB * DD;
        const float* t2dB = g_t2 + (size_t)dnB * DD;
#pragma unroll
        for (int j = 0; j < 8; j++) {
            int c = nbase + j * 8 + 2 * t;
            float2 d1 = *(const float2*)(db + c);
            float2 d2 = *(const float2*)(eb + c);
            float bx = d1.x + d2.x, by = d1.y + d2.y;

            float2 p1 = *(const float2*)(t1A + c);
            float2 p2 = *(const float2*)(t2sA + c);
            float2 p3 = *(const float2*)(t2dA + c);
            float2 oA;
            oA.x = fmaxf(acc[mt][j][0] + p1.x + 0.5f * (p2.x + p3.x) + bx, 0.f);
            oA.y = fmaxf(acc[mt][j][1] + p1.y + 0.5f * (p2.y + p3.y) + by, 0.f);
            *(float2*)(out + (size_t)e * DD + c) = oA;

            float2 q1 = *(const float2*)(t1B + c);
            float2 q2 = *(const float2*)(t2sB + c);
            float2 q3 = *(const float2*)(t2dB + c);
            float2 oB;
            oB.x = fmaxf(acc[mt][j][2] + q1.x + 0.5f * (q2.x + q3.x) + bx, 0.f);
            oB.y = fmaxf(acc[mt][j][3] + q1.y + 0.5f * (q2.y + q3.y) + by, 0.f);
            *(float2*)(out + (size_t)(e + 8) * DD + c) = oB;
        }
    }
}

// ---------------- launch ------------------------------------------------------
extern "C" void kernel_launch(void* const* d_in, const int* in_sizes, int n_in,
                              void* d_out, int out_size) {
    (void)in_sizes; (void)n_in; (void)out_size;
    const float* nf        = (const float*)d_in[0];
    const float* ef        = (const float*)d_in[1];
    const float* W_node    = (const float*)d_in[2];
    const float* W_edge    = (const float*)d_in[3];
    const float* node_bias = (const float*)d_in[4];
    const float* edge_bias = (const float*)d_in[5];
    const float* dense_W   = (const float*)d_in[6];
    const float* dense_b   = (const float*)d_in[7];
    const int*   src       = (const int*)d_in[8];
    const int*   dst       = (const int*)d_in[9];

    float* nf2 = (float*)d_out;
    float* ef2 = (float*)d_out + (size_t)NN * DD;

    cudaFuncSetAttribute(node_mm, cudaFuncAttributeMaxDynamicSharedMemorySize, SMEM_BYTES);
    cudaFuncSetAttribute(edge_out_gemm, cudaFuncAttributeMaxDynamicSharedMemorySize, SMEM_BYTES);

    const int NBLK = (NN + 127) / 128;

    zero_kernel<<<1024, 256>>>();
    split_w_node<<<64, 256>>>(W_node);
    split_w_edge<<<64, 256>>>(W_edge);
    split_w_d1<<<64, 256>>>(dense_W);
    split_w_d2<<<64, 256>>>(dense_W);
    make_M<<<128, 128>>>(W_edge, dense_W);
    split_M<<<64, 256>>>();

    scatter_ef<<<NE / 8, 256>>>(ef, dst);                       // S, deg
    node_mm<<<NBLK, 256, SMEM_BYTES>>>(0, nf, node_bias, nf2);  // nf2
    node_mm<<<NBLK, 256, SMEM_BYTES>>>(1, nullptr, nullptr, nullptr); // nb
    node_mm<<<NBLK, 256, SMEM_BYTES>>>(2, nullptr, nullptr, nullptr); // t1
    node_mm<<<NBLK, 256, SMEM_BYTES>>>(3, nf2, nullptr, nullptr);     // t2
    edge_out_gemm<<<NE / 128, 256, SMEM_BYTES>>>(ef, src, dst, dense_b,
                                                 edge_bias, ef2);
}

// round 10
// speedup vs baseline: 1.9161x; 1.1477x over previous
#include <cuda_runtime.h>
#include <cuda_bf16.h>
#include <cstdint>

#define NN 50000
#define NE 800000
#define DD 128

// ---------------- scratch (device globals; referenced ONLY in device code) ----
__device__ float g_s[(size_t)NN * DD];    // segment_sum(ef, dst)
__device__ float g_deg[NN];
__device__ float g_t2[(size_t)NN * DD];   // nf2 @ Wd2
__device__ float g_t3[(size_t)NN * DD];   // nb@Wd1 + 0.5 * t2
__device__ float g_M[DD * DD];            // We @ Wd1 (fp32)
// bf16 hi/lo splits, B layout: B[n][k] = W[k][n]
__device__ __nv_bfloat16 g_Bn_h[DD * DD], g_Bn_l[DD * DD];     // W_node
__device__ __nv_bfloat16 g_Be_h[DD * DD], g_Be_l[DD * DD];     // W_edge
__device__ __nv_bfloat16 g_Bd1_h[DD * DD], g_Bd1_l[DD * DD];   // dense_W[0:128]
__device__ __nv_bfloat16 g_Bd2_h[DD * DD], g_Bd2_l[DD * DD];   // dense_W[128:256]
__device__ __nv_bfloat16 g_Bm_h[DD * DD], g_Bm_l[DD * DD];     // M = We@Wd1

// ---------------- smem layout (32-bit words) ----------------------------------
#define WPAD 68
#define SA_H 0
#define SA_L (128 * WPAD)
#define SB_H (2 * 128 * WPAD)
#define SB_L (3 * 128 * WPAD)
#define SMEM_BYTES (4 * 128 * WPAD * 4)   // 139264

// ---------------- helpers ------------------------------------------------------
__device__ __forceinline__ void split2(float x, float y, uint32_t& hi, uint32_t& lo) {
    __nv_bfloat162 h = __floats2bfloat162_rn(x, y);
    hi = *(uint32_t*)&h;
    float rx = x - __bfloat162float(__low2bfloat16(h));
    float ry = y - __bfloat162float(__high2bfloat16(h));
    __nv_bfloat162 l = __floats2bfloat162_rn(rx, ry);
    lo = *(uint32_t*)&l;
}

__device__ __forceinline__ void mma_bf16(float* d, const uint32_t* a,
                                         uint32_t b0, uint32_t b1) {
    asm volatile(
        "mma.sync.aligned.m16n8k16.row.col.f32.bf16.bf16.f32 "
        "{%0,%1,%2,%3}, {%4,%5,%6,%7}, {%8,%9}, {%0,%1,%2,%3};"
        : "+f"(d[0]), "+f"(d[1]), "+f"(d[2]), "+f"(d[3])
        : "r"(a[0]), "r"(a[1]), "r"(a[2]), "r"(a[3]), "r"(b0), "r"(b1));
}

__device__ __forceinline__ void fillB(uint32_t* sm, const __nv_bfloat16* bh,
                                      const __nv_bfloat16* bl, int tid) {
#pragma unroll
    for (int i = 0; i < 32; i++) {
        int idx = tid + i * 256;
        int n = idx >> 6, w = idx & 63;
        sm[SB_H + n * WPAD + w] = *(const uint32_t*)(bh + (size_t)n * DD + 2 * w);
        sm[SB_L + n * WPAD + w] = *(const uint32_t*)(bl + (size_t)n * DD + 2 * w);
    }
}

// K=128 compute loop: warp computes 32 rows x 64 cols with 3-way bf16 split
__device__ __forceinline__ void kloop(const uint32_t* sm, int lane, int mbase,
                                      int nbase, float acc[2][8][4]) {
    const int g = lane >> 2, t = lane & 3;
#pragma unroll
    for (int ks = 0; ks < 8; ks++) {
        const int kw = ks * 8 + t;
        uint32_t ah[2][4], al[2][4];
#pragma unroll
        for (int mt = 0; mt < 2; mt++) {
            int r = mbase + mt * 16 + g;
            ah[mt][0] = sm[SA_H + r * WPAD + kw];
            ah[mt][1] = sm[SA_H + (r + 8) * WPAD + kw];
            ah[mt][2] = sm[SA_H + r * WPAD + kw + 4];
            ah[mt][3] = sm[SA_H + (r + 8) * WPAD + kw + 4];
            al[mt][0] = sm[SA_L + r * WPAD + kw];
            al[mt][1] = sm[SA_L + (r + 8) * WPAD + kw];
            al[mt][2] = sm[SA_L + r * WPAD + kw + 4];
            al[mt][3] = sm[SA_L + (r + 8) * WPAD + kw + 4];
        }
#pragma unroll
        for (int j = 0; j < 8; j++) {
            int n = nbase + j * 8 + g;
            uint32_t bh0 = sm[SB_H + n * WPAD + kw];
            uint32_t bh1 = sm[SB_H + n * WPAD + kw + 4];
            uint32_t bl0 = sm[SB_L + n * WPAD + kw];
            uint32_t bl1 = sm[SB_L + n * WPAD + kw + 4];
#pragma unroll
            for (int mt = 0; mt < 2; mt++) {
                mma_bf16(acc[mt][j], ah[mt], bh0, bh1);
                mma_bf16(acc[mt][j], ah[mt], bl0, bl1);
                mma_bf16(acc[mt][j], al[mt], bh0, bh1);
            }
        }
    }
}

__device__ __forceinline__ void zero_acc(float acc[2][8][4]) {
#pragma unroll
    for (int a = 0; a < 2; a++)
#pragma unroll
        for (int b = 0; b < 8; b++)
#pragma unroll
            for (int c = 0; c < 4; c++) acc[a][b][c] = 0.f;
}

// write warp's acc patch back into the smem A tile (bf16 hi/lo re-split)
__device__ __forceinline__ void acc_to_sa(uint32_t* sm, const float acc[2][8][4],
                                          int mbase, int nbase, int lane) {
    const int g = lane >> 2, t = lane & 3;
#pragma unroll
    for (int mt = 0; mt < 2; mt++) {
        int rA = mbase + mt * 16 + g, rB = rA + 8;
#pragma unroll
        for (int j = 0; j < 8; j++) {
            int w = (nbase >> 1) + j * 4 + t;
            uint32_t hi, lo;
            split2(acc[mt][j][0], acc[mt][j][1], hi, lo);
            sm[SA_H + rA * WPAD + w] = hi;
            sm[SA_L + rA * WPAD + w] = lo;
            split2(acc[mt][j][2], acc[mt][j][3], hi, lo);
            sm[SA_H + rB * WPAD + w] = hi;
            sm[SA_L + rB * WPAD + w] = lo;
        }
    }
}

// ---------------- prep kernels --------------------------------------------------
__global__ void zero_kernel() {
    int stride = gridDim.x * blockDim.x;
    int t = blockIdx.x * blockDim.x + threadIdx.x;
    for (int i = t; i < NN * DD; i += stride) g_s[i] = 0.0f;
    for (int i = t; i < NN; i += stride) g_deg[i] = 0.0f;
}

// scatter raw ef into g_s[dst] + degree, via vector reductions (sm_90+)
__global__ __launch_bounds__(256)
void scatter_ef(const float* __restrict__ ef, const int* __restrict__ dst) {
    int gw = (blockIdx.x * 256 + threadIdx.x) >> 5;   // global warp = edge
    int lane = threadIdx.x & 31;
    if (gw >= NE) return;
    int dn = dst[gw];
    float4 v = ((const float4*)(ef + (size_t)gw * DD))[lane];
    float* sp = g_s + (size_t)dn * DD + lane * 4;
    asm volatile("red.global.add.v4.f32 [%0], {%1,%2,%3,%4};"
                 :: "l"(sp), "f"(v.x), "f"(v.y), "f"(v.z), "f"(v.w) : "memory");
    if (lane == 0)
        asm volatile("red.global.add.f32 [%0], %1;"
                     :: "l"(g_deg + dn), "f"(1.0f) : "memory");
}

// transpose + bf16-split: W is [128,128] row-major (k rows), dest B[n][k]
__device__ __forceinline__ void split_one(const float* W, int idx,
                                          __nv_bfloat16* Bh, __nv_bfloat16* Bl) {
    int n = idx >> 7, k = idx & 127;
    float v = W[(size_t)k * DD + n];
    __nv_bfloat16 h = __float2bfloat16(v);
    Bh[idx] = h;
    Bl[idx] = __float2bfloat16(v - __bfloat162float(h));
}
__global__ void split_w_node(const float* __restrict__ W) {
    int idx = blockIdx.x * blockDim.x + threadIdx.x;
    if (idx < DD * DD) split_one(W, idx, g_Bn_h, g_Bn_l);
}
__global__ void split_w_edge(const float* __restrict__ W) {
    int idx = blockIdx.x * blockDim.x + threadIdx.x;
    if (idx < DD * DD) split_one(W, idx, g_Be_h, g_Be_l);
}
__global__ void split_w_d1(const float* __restrict__ dW) {
    int idx = blockIdx.x * blockDim.x + threadIdx.x;
    if (idx < DD * DD) split_one(dW, idx, g_Bd1_h, g_Bd1_l);
}
__global__ void split_w_d2(const float* __restrict__ dW) {
    int idx = blockIdx.x * blockDim.x + threadIdx.x;
    if (idx < DD * DD) split_one(dW + DD * DD, idx, g_Bd2_h, g_Bd2_l);
}

// M = We @ Wd1 in fp32
__global__ void make_M(const float* __restrict__ We, const float* __restrict__ dW) {
    int k = blockIdx.x, n = threadIdx.x;
    float s = 0.f;
#pragma unroll 4
    for (int j = 0; j < DD; j++)
        s = fmaf(We[(size_t)k * DD + j], dW[(size_t)j * DD + n], s);
    g_M[k * DD + n] = s;
}
__global__ void split_M() {
    int idx = blockIdx.x * blockDim.x + threadIdx.x;
    if (idx < DD * DD) split_one(g_M, idx, g_Bm_h, g_Bm_l);
}

// ---------------- fused node pass A: nf2 = relu(nf@Wn + b); t2 = nf2@Wd2 -------
__global__ __launch_bounds__(256, 1)
void node_pass_a(const float* __restrict__ nf, const float* __restrict__ bias,
                 float* __restrict__ nf2out) {
    extern __shared__ uint32_t sm[];
    const int tid = threadIdx.x, lane = tid & 31, wid = tid >> 5;
    const int rowbase = blockIdx.x * 128;
    const int mbase = (wid & 3) * 32, nbase = (wid >> 2) * 64;
    const int g = lane >> 2, t = lane & 3;

    fillB(sm, g_Bn_h, g_Bn_l, tid);
#pragma unroll
    for (int i = 0; i < 32; i++) {
        int idx = tid + i * 256;
        int r = idx >> 6, w = idx & 63;
        int row = rowbase + r;
        float2 v = make_float2(0.f, 0.f);
        if (row < NN) v = *(const float2*)(nf + (size_t)row * DD + 2 * w);
        split2(v.x, v.y, sm[SA_H + r * WPAD + w], sm[SA_L + r * WPAD + w]);
    }
    __syncthreads();

    float acc[2][8][4];
    zero_acc(acc);
    kloop(sm, lane, mbase, nbase, acc);
    __syncthreads();                      // everyone done reading SA/SB

    // epilogue 1: bias + relu -> nf2 (global) and re-split into SA
#pragma unroll
    for (int mt = 0; mt < 2; mt++) {
        int rowA = rowbase + mbase + mt * 16 + g;
#pragma unroll
        for (int j = 0; j < 8; j++) {
            int c = nbase + j * 8 + 2 * t;
            float2 bv = *(const float2*)(bias + c);
            acc[mt][j][0] = fmaxf(acc[mt][j][0] + bv.x, 0.f);
            acc[mt][j][1] = fmaxf(acc[mt][j][1] + bv.y, 0.f);
            acc[mt][j][2] = fmaxf(acc[mt][j][2] + bv.x, 0.f);
            acc[mt][j][3] = fmaxf(acc[mt][j][3] + bv.y, 0.f);
            if (rowA < NN)
                *(float2*)(nf2out + (size_t)rowA * DD + c) =
                    make_float2(acc[mt][j][0], acc[mt][j][1]);
            if (rowA + 8 < NN)
                *(float2*)(nf2out + (size_t)(rowA + 8) * DD + c) =
                    make_float2(acc[mt][j][2], acc[mt][j][3]);
        }
    }
    acc_to_sa(sm, acc, mbase, nbase, lane);
    fillB(sm, g_Bd2_h, g_Bd2_l, tid);
    __syncthreads();

    zero_acc(acc);
    kloop(sm, lane, mbase, nbase, acc);

#pragma unroll
    for (int mt = 0; mt < 2; mt++) {
        int rowA = rowbase + mbase + mt * 16 + g;
#pragma unroll
        for (int j = 0; j < 8; j++) {
            int c = nbase + j * 8 + 2 * t;
            if (rowA < NN)
                *(float2*)(g_t2 + (size_t)rowA * DD + c) =
                    make_float2(acc[mt][j][0], acc[mt][j][1]);
            if (rowA + 8 < NN)
                *(float2*)(g_t2 + (size_t)(rowA + 8) * DD + c) =
                    make_float2(acc[mt][j][2], acc[mt][j][3]);
        }
    }
}

// ---------------- fused node pass B: nb = (S@We)/deg; t3 = nb@Wd1 + 0.5*t2 -----
__global__ __launch_bounds__(256, 1)
void node_pass_b() {
    extern __shared__ uint32_t sm[];
    const int tid = threadIdx.x, lane = tid & 31, wid = tid >> 5;
    const int rowbase = blockIdx.x * 128;
    const int mbase = (wid & 3) * 32, nbase = (wid >> 2) * 64;
    const int g = lane >> 2, t = lane & 3;

    fillB(sm, g_Be_h, g_Be_l, tid);
#pragma unroll
    for (int i = 0; i < 32; i++) {
        int idx = tid + i * 256;
        int r = idx >> 6, w = idx & 63;
        int row = rowbase + r;
        float2 v = make_float2(0.f, 0.f);
        if (row < NN) v = *(const float2*)(g_s + (size_t)row * DD + 2 * w);
        split2(v.x, v.y, sm[SA_H + r * WPAD + w], sm[SA_L + r * WPAD + w]);
    }
    __syncthreads();

    float acc[2][8][4];
    zero_acc(acc);
    kloop(sm, lane, mbase, nbase, acc);
    __syncthreads();

    // scale by 1/max(deg,1) and re-split into SA
#pragma unroll
    for (int mt = 0; mt < 2; mt++) {
        int rowA = rowbase + mbase + mt * 16 + g;
        float s0 = 1.f, s1 = 1.f;
        if (rowA < NN) s0 = 1.f / fmaxf(g_deg[rowA], 1.f);
        if (rowA + 8 < NN) s1 = 1.f / fmaxf(g_deg[rowA + 8], 1.f);
#pragma unroll
        for (int j = 0; j < 8; j++) {
            acc[mt][j][0] *= s0; acc[mt][j][1] *= s0;
            acc[mt][j][2] *= s1; acc[mt][j][3] *= s1;
        }
    }
    acc_to_sa(sm, acc, mbase, nbase, lane);
    fillB(sm, g_Bd1_h, g_Bd1_l, tid);
    __syncthreads();

    zero_acc(acc);
    kloop(sm, lane, mbase, nbase, acc);

#pragma unroll
    for (int mt = 0; mt < 2; mt++) {
        int rowA = rowbase + mbase + mt * 16 + g;
#pragma unroll
        for (int j = 0; j < 8; j++) {
            int c = nbase + j * 8 + 2 * t;
            if (rowA < NN) {
                float2 u = *(const float2*)(g_t2 + (size_t)rowA * DD + c);
                *(float2*)(g_t3 + (size_t)rowA * DD + c) =
                    make_float2(acc[mt][j][0] + 0.5f * u.x,
                                acc[mt][j][1] + 0.5f * u.y);
            }
            if (rowA + 8 < NN) {
                float2 u = *(const float2*)(g_t2 + (size_t)(rowA + 8) * DD + c);
                *(float2*)(g_t3 + (size_t)(rowA + 8) * DD + c) =
                    make_float2(acc[mt][j][2] + 0.5f * u.x,
                                acc[mt][j][3] + 0.5f * u.y);
            }
        }
    }
}

// ---------------- fused edge output kernel -------------------------------------
// ef2 = relu(ef @ M + t3[dst] + 0.5*t2[src] + db + eb)
__global__ __launch_bounds__(256, 1)
void edge_out_gemm(const float* __restrict__ ef, const int* __restrict__ src,
                   const int* __restrict__ dst, const float* __restrict__ db,
                   const float* __restrict__ eb, float* __restrict__ out) {
    extern __shared__ uint32_t sm[];
    const int tid = threadIdx.x, lane = tid & 31, wid = tid >> 5;
    const int e0 = blockIdx.x * 128;

    fillB(sm, g_Bm_h, g_Bm_l, tid);
#pragma unroll
    for (int i = 0; i < 32; i++) {
        int idx = tid + i * 256;
        int r = idx >> 6, w = idx & 63;
        float2 v = *(const float2*)(ef + (size_t)(e0 + r) * DD + 2 * w);
        split2(v.x, v.y, sm[SA_H + r * WPAD + w], sm[SA_L + r * WPAD + w]);
    }
    __syncthreads();

    const int mbase = (wid & 3) * 32, nbase = (wid >> 2) * 64;
    float acc[2][8][4];
    zero_acc(acc);
    kloop(sm, lane, mbase, nbase, acc);

    const int g = lane >> 2, t = lane & 3;
#pragma unroll
    for (int mt = 0; mt < 2; mt++) {
        int e = e0 + mbase + mt * 16 + g;
        int dnA = dst[e], snA = src[e];
        int dnB = dst[e + 8], snB = src[e + 8];
        const float* t3A = g_t3 + (size_t)dnA * DD;
        const float* t2A = g_t2 + (size_t)snA * DD;
        const float* t3B = g_t3 + (size_t)dnB * DD;
        const float* t2B = g_t2 + (size_t)snB * DD;
#pragma unroll
        for (int j = 0; j < 8; j++) {
            int c = nbase + j * 8 + 2 * t;
            float2 d1 = *(const float2*)(db + c);
            float2 d2 = *(const float2*)(eb + c);
            float bx = d1.x + d2.x, by = d1.y + d2.y;

            float2 p1 = *(const float2*)(t3A + c);
            float2 p2 = *(const float2*)(t2A + c);
            float2 oA;
            oA.x = fmaxf(acc[mt][j][0] + p1.x + 0.5f * p2.x + bx, 0.f);
            oA.y = fmaxf(acc[mt][j][1] + p1.y + 0.5f * p2.y + by, 0.f);
            *(float2*)(out + (size_t)e * DD + c) = oA;

            float2 q1 = *(const float2*)(t3B + c);
            float2 q2 = *(const float2*)(t2B + c);
            float2 oB;
            oB.x = fmaxf(acc[mt][j][2] + q1.x + 0.5f * q2.x + bx, 0.f);
            oB.y = fmaxf(acc[mt][j][3] + q1.y + 0.5f * q2.y + by, 0.f);
            *(float2*)(out + (size_t)(e + 8) * DD + c) = oB;
        }
    }
}

// ---------------- launch ------------------------------------------------------
extern "C" void kernel_launch(void* const* d_in, const int* in_sizes, int n_in,
                              void* d_out, int out_size) {
    (void)in_sizes; (void)n_in; (void)out_size;
    const float* nf        = (const float*)d_in[0];
    const float* ef        = (const float*)d_in[1];
    const float* W_node    = (const float*)d_in[2];
    const float* W_edge    = (const float*)d_in[3];
    const float* node_bias = (const float*)d_in[4];
    const float* edge_bias = (const float*)d_in[5];
    const float* dense_W   = (const float*)d_in[6];
    const float* dense_b   = (const float*)d_in[7];
    const int*   src       = (const int*)d_in[8];
    const int*   dst       = (const int*)d_in[9];

    float* nf2 = (float*)d_out;
    float* ef2 = (float*)d_out + (size_t)NN * DD;

    cudaFuncSetAttribute(node_pass_a, cudaFuncAttributeMaxDynamicSharedMemorySize, SMEM_BYTES);
    cudaFuncSetAttribute(node_pass_b, cudaFuncAttributeMaxDynamicSharedMemorySize, SMEM_BYTES);
    cudaFuncSetAttribute(edge_out_gemm, cudaFuncAttributeMaxDynamicSharedMemorySize, SMEM_BYTES);

    const int NBLK = (NN + 127) / 128;

    zero_kernel<<<1024, 256>>>();
    split_w_node<<<64, 256>>>(W_node);
    split_w_edge<<<64, 256>>>(W_edge);
    split_w_d1<<<64, 256>>>(dense_W);
    split_w_d2<<<64, 256>>>(dense_W);
    make_M<<<128, 128>>>(W_edge, dense_W);
    split_M<<<64, 256>>>();

    scatter_ef<<<NE / 8, 256>>>(ef, dst);                        // S, deg
    node_pass_a<<<NBLK, 256, SMEM_BYTES>>>(nf, node_bias, nf2);  // nf2, t2
    node_pass_b<<<NBLK, 256, SMEM_BYTES>>>();                    // t3
    edge_out_gemm<<<NE / 128, 256, SMEM_BYTES>>>(ef, src, dst, dense_b,
                                                 edge_bias, ef2);
}

// round 11
// speedup vs baseline: 2.3339x; 1.2180x over previous
#include <cuda_runtime.h>
#include <cuda_bf16.h>
#include <cstdint>

#define NN 50000
#define NE 800000
#define DD 128

// ---------------- scratch (device globals; referenced ONLY in device code) ----
__device__ __align__(512) float g_s[(size_t)NN * DD];   // segment_sum(ef, dst)
__device__ float g_deg[NN];
__device__ float g_t2[(size_t)NN * DD];   // nf2 @ Wd2
__device__ float g_t3[(size_t)NN * DD];   // (S/deg)@M + 0.5 * t2
// bf16 hi/lo splits, B layout: B[n][k] = W[k][n]
__device__ __nv_bfloat16 g_Bn_h[DD * DD], g_Bn_l[DD * DD];     // W_node
__device__ __nv_bfloat16 g_Bd2_h[DD * DD], g_Bd2_l[DD * DD];   // dense_W[128:256]
__device__ __nv_bfloat16 g_Bm_h[DD * DD], g_Bm_l[DD * DD];     // M = We@Wd1

// ---------------- smem layout (32-bit words) ----------------------------------
#define WPAD 68
#define SA_H 0
#define SA_L (128 * WPAD)
#define SB_H (2 * 128 * WPAD)
#define SB_L (3 * 128 * WPAD)
#define SMEM_BYTES (4 * 128 * WPAD * 4)   // 139264
#define SCAT_SMEM 65536

// ---------------- helpers ------------------------------------------------------
__device__ __forceinline__ uint32_t smem_u32(const void* p) {
    uint32_t a;
    asm("{ .reg .u64 t; cvta.to.shared.u64 t, %1; cvt.u32.u64 %0, t; }" : "=r"(a) : "l"(p));
    return a;
}

__device__ __forceinline__ void split2(float x, float y, uint32_t& hi, uint32_t& lo) {
    __nv_bfloat162 h = __floats2bfloat162_rn(x, y);
    hi = *(uint32_t*)&h;
    float rx = x - __bfloat162float(__low2bfloat16(h));
    float ry = y - __bfloat162float(__high2bfloat16(h));
    __nv_bfloat162 l = __floats2bfloat162_rn(rx, ry);
    lo = *(uint32_t*)&l;
}

__device__ __forceinline__ void mma_bf16(float* d, const uint32_t* a,
                                         uint32_t b0, uint32_t b1) {
    asm volatile(
        "mma.sync.aligned.m16n8k16.row.col.f32.bf16.bf16.f32 "
        "{%0,%1,%2,%3}, {%4,%5,%6,%7}, {%8,%9}, {%0,%1,%2,%3};"
        : "+f"(d[0]), "+f"(d[1]), "+f"(d[2]), "+f"(d[3])
        : "r"(a[0]), "r"(a[1]), "r"(a[2]), "r"(a[3]), "r"(b0), "r"(b1));
}

// 512 threads fill the B tile pair
__device__ __forceinline__ void fillB(uint32_t* sm, const __nv_bfloat16* bh,
                                      const __nv_bfloat16* bl, int tid) {
#pragma unroll
    for (int i = 0; i < 16; i++) {
        int idx = tid + i * 512;
        int n = idx >> 6, w = idx & 63;
        sm[SB_H + n * WPAD + w] = *(const uint32_t*)(bh + (size_t)n * DD + 2 * w);
        sm[SB_L + n * WPAD + w] = *(const uint32_t*)(bl + (size_t)n * DD + 2 * w);
    }
}

// K=128 loop: warp computes 32 rows x 32 cols with 3-way bf16 split
__device__ __forceinline__ void kloop(const uint32_t* sm, int lane, int mbase,
                                      int nbase, float acc[2][4][4]) {
    const int g = lane >> 2, t = lane & 3;
#pragma unroll
    for (int ks = 0; ks < 8; ks++) {
        const int kw = ks * 8 + t;
        uint32_t ah[2][4], al[2][4];
#pragma unroll
        for (int mt = 0; mt < 2; mt++) {
            int r = mbase + mt * 16 + g;
            ah[mt][0] = sm[SA_H + r * WPAD + kw];
            ah[mt][1] = sm[SA_H + (r + 8) * WPAD + kw];
            ah[mt][2] = sm[SA_H + r * WPAD + kw + 4];
            ah[mt][3] = sm[SA_H + (r + 8) * WPAD + kw + 4];
            al[mt][0] = sm[SA_L + r * WPAD + kw];
            al[mt][1] = sm[SA_L + (r + 8) * WPAD + kw];
            al[mt][2] = sm[SA_L + r * WPAD + kw + 4];
            al[mt][3] = sm[SA_L + (r + 8) * WPAD + kw + 4];
        }
#pragma unroll
        for (int j = 0; j < 4; j++) {
            int n = nbase + j * 8 + g;
            uint32_t bh0 = sm[SB_H + n * WPAD + kw];
            uint32_t bh1 = sm[SB_H + n * WPAD + kw + 4];
            uint32_t bl0 = sm[SB_L + n * WPAD + kw];
            uint32_t bl1 = sm[SB_L + n * WPAD + kw + 4];
#pragma unroll
            for (int mt = 0; mt < 2; mt++) {
                mma_bf16(acc[mt][j], ah[mt], bh0, bh1);
                mma_bf16(acc[mt][j], ah[mt], bl0, bl1);
                mma_bf16(acc[mt][j], al[mt], bh0, bh1);
            }
        }
    }
}

__device__ __forceinline__ void zero_acc(float acc[2][4][4]) {
#pragma unroll
    for (int a = 0; a < 2; a++)
#pragma unroll
        for (int b = 0; b < 4; b++)
#pragma unroll
            for (int c = 0; c < 4; c++) acc[a][b][c] = 0.f;
}

// write warp's acc patch back into the smem A tile (bf16 hi/lo re-split)
__device__ __forceinline__ void acc_to_sa(uint32_t* sm, const float acc[2][4][4],
                                          int mbase, int nbase, int lane) {
    const int g = lane >> 2, t = lane & 3;
#pragma unroll
    for (int mt = 0; mt < 2; mt++) {
        int rA = mbase + mt * 16 + g, rB = rA + 8;
#pragma unroll
        for (int j = 0; j < 4; j++) {
            int w = (nbase >> 1) + j * 4 + t;
            uint32_t hi, lo;
            split2(acc[mt][j][0], acc[mt][j][1], hi, lo);
            sm[SA_H + rA * WPAD + w] = hi;
            sm[SA_L + rA * WPAD + w] = lo;
            split2(acc[mt][j][2], acc[mt][j][3], hi, lo);
            sm[SA_H + rB * WPAD + w] = hi;
            sm[SA_L + rB * WPAD + w] = lo;
        }
    }
}

// ---------------- prep kernels --------------------------------------------------
__global__ void zero_kernel() {
    int stride = gridDim.x * blockDim.x;
    int t = blockIdx.x * blockDim.x + threadIdx.x;
    for (int i = t; i < NN * DD; i += stride) g_s[i] = 0.0f;
    for (int i = t; i < NN; i += stride) g_deg[i] = 0.0f;
}

// one kernel: splits of W_node, dense_W[128:], and M=We@Wd1 (dot inline)
__global__ void prep_weights(const float* __restrict__ Wn,
                             const float* __restrict__ We,
                             const float* __restrict__ dW) {
    int idx = blockIdx.x * blockDim.x + threadIdx.x;
    if (idx >= DD * DD) return;
    int n = idx >> 7, k = idx & 127;

    float v = Wn[(size_t)k * DD + n];
    __nv_bfloat16 h = __float2bfloat16(v);
    g_Bn_h[idx] = h;
    g_Bn_l[idx] = __float2bfloat16(v - __bfloat162float(h));

    v = dW[(size_t)(128 + k) * DD + n];
    h = __float2bfloat16(v);
    g_Bd2_h[idx] = h;
    g_Bd2_l[idx] = __float2bfloat16(v - __bfloat162float(h));

    float m = 0.f;
#pragma unroll 4
    for (int j = 0; j < DD; j++)
        m = fmaf(We[(size_t)k * DD + j], dW[(size_t)j * DD + n], m);
    h = __float2bfloat16(m);
    g_Bm_h[idx] = h;
    g_Bm_l[idx] = __float2bfloat16(m - __bfloat162float(h));
}

// scatter 128 contiguous ef rows via smem + TMA bulk reductions
__global__ __launch_bounds__(256)
void scatter_ef(const float* __restrict__ ef, const int* __restrict__ dst) {
    extern __shared__ __align__(16) float buf[];   // 128 rows x 128 f32 = 64KB
    const int tid = threadIdx.x;
    const int e0 = blockIdx.x * 128;
    const float4* src = (const float4*)(ef + (size_t)e0 * DD);
    float4* b4 = (float4*)buf;
#pragma unroll
    for (int i = 0; i < 16; i++)
        b4[tid + i * 256] = src[tid + i * 256];
    __syncthreads();
    asm volatile("fence.proxy.async.shared::cta;" ::: "memory");
    if (tid < 128) {
        int e = e0 + tid;
        int dn = dst[e];
        uint32_t sptr = smem_u32(buf + tid * DD);
        float* gptr = g_s + (size_t)dn * DD;
        asm volatile(
            "cp.reduce.async.bulk.global.shared::cta.bulk_group.add.f32 [%0], [%1], 512;"
            :: "l"(gptr), "r"(sptr) : "memory");
        asm volatile("red.global.add.f32 [%0], %1;"
                     :: "l"(g_deg + dn), "f"(1.0f) : "memory");
    }
    asm volatile("cp.async.bulk.commit_group;" ::: "memory");
    asm volatile("cp.async.bulk.wait_group 0;" ::: "memory");
}

// ---------------- fused node pass A: nf2 = relu(nf@Wn + b); t2 = nf2@Wd2 -------
__global__ __launch_bounds__(512, 1)
void node_pass_a(const float* __restrict__ nf, const float* __restrict__ bias,
                 float* __restrict__ nf2out) {
    extern __shared__ uint32_t sm[];
    const int tid = threadIdx.x, lane = tid & 31, wid = tid >> 5;
    const int rowbase = blockIdx.x * 128;
    const int mbase = (wid & 3) * 32, nbase = (wid >> 2) * 32;
    const int g = lane >> 2, t = lane & 3;

    fillB(sm, g_Bn_h, g_Bn_l, tid);
#pragma unroll
    for (int i = 0; i < 16; i++) {
        int idx = tid + i * 512;
        int r = idx >> 6, w = idx & 63;
        int row = rowbase + r;
        float2 v = make_float2(0.f, 0.f);
        if (row < NN) v = *(const float2*)(nf + (size_t)row * DD + 2 * w);
        split2(v.x, v.y, sm[SA_H + r * WPAD + w], sm[SA_L + r * WPAD + w]);
    }
    __syncthreads();

    float acc[2][4][4];
    zero_acc(acc);
    kloop(sm, lane, mbase, nbase, acc);
    __syncthreads();

    // epilogue 1: bias + relu -> nf2 (global) and re-split into SA
#pragma unroll
    for (int mt = 0; mt < 2; mt++) {
        int rowA = rowbase + mbase + mt * 16 + g;
#pragma unroll
        for (int j = 0; j < 4; j++) {
            int c = nbase + j * 8 + 2 * t;
            float2 bv = *(const float2*)(bias + c);
            acc[mt][j][0] = fmaxf(acc[mt][j][0] + bv.x, 0.f);
            acc[mt][j][1] = fmaxf(acc[mt][j][1] + bv.y, 0.f);
            acc[mt][j][2] = fmaxf(acc[mt][j][2] + bv.x, 0.f);
            acc[mt][j][3] = fmaxf(acc[mt][j][3] + bv.y, 0.f);
            if (rowA < NN)
                *(float2*)(nf2out + (size_t)rowA * DD + c) =
                    make_float2(acc[mt][j][0], acc[mt][j][1]);
            if (rowA + 8 < NN)
                *(float2*)(nf2out + (size_t)(rowA + 8) * DD + c) =
                    make_float2(acc[mt][j][2], acc[mt][j][3]);
        }
    }
    acc_to_sa(sm, acc, mbase, nbase, lane);
    fillB(sm, g_Bd2_h, g_Bd2_l, tid);
    __syncthreads();

    zero_acc(acc);
    kloop(sm, lane, mbase, nbase, acc);

#pragma unroll
    for (int mt = 0; mt < 2; mt++) {
        int rowA = rowbase + mbase + mt * 16 + g;
#pragma unroll
        for (int j = 0; j < 4; j++) {
            int c = nbase + j * 8 + 2 * t;
            if (rowA < NN)
                *(float2*)(g_t2 + (size_t)rowA * DD + c) =
                    make_float2(acc[mt][j][0], acc[mt][j][1]);
            if (rowA + 8 < NN)
                *(float2*)(g_t2 + (size_t)(rowA + 8) * DD + c) =
                    make_float2(acc[mt][j][2], acc[mt][j][3]);
        }
    }
}

// ---------------- node pass B: t3 = (S/deg) @ M + 0.5*t2 ------------------------
__global__ __launch_bounds__(512, 1)
void node_pass_b() {
    extern __shared__ uint32_t sm[];
    const int tid = threadIdx.x, lane = tid & 31, wid = tid >> 5;
    const int rowbase = blockIdx.x * 128;
    const int mbase = (wid & 3) * 32, nbase = (wid >> 2) * 32;
    const int g = lane >> 2, t = lane & 3;

    fillB(sm, g_Bm_h, g_Bm_l, tid);
#pragma unroll
    for (int i = 0; i < 16; i++) {
        int idx = tid + i * 512;
        int r = idx >> 6, w = idx & 63;
        int row = rowbase + r;
        float2 v = make_float2(0.f, 0.f);
        if (row < NN) {
            float s = 1.f / fmaxf(g_deg[row], 1.f);
            v = *(const float2*)(g_s + (size_t)row * DD + 2 * w);
            v.x *= s; v.y *= s;
        }
        split2(v.x, v.y, sm[SA_H + r * WPAD + w], sm[SA_L + r * WPAD + w]);
    }
    __syncthreads();

    float acc[2][4][4];
    zero_acc(acc);
    kloop(sm, lane, mbase, nbase, acc);

#pragma unroll
    for (int mt = 0; mt < 2; mt++) {
        int rowA = rowbase + mbase + mt * 16 + g;
#pragma unroll
        for (int j = 0; j < 4; j++) {
            int c = nbase + j * 8 + 2 * t;
            if (rowA < NN) {
                float2 u = *(const float2*)(g_t2 + (size_t)rowA * DD + c);
                *(float2*)(g_t3 + (size_t)rowA * DD + c) =
                    make_float2(acc[mt][j][0] + 0.5f * u.x,
                                acc[mt][j][1] + 0.5f * u.y);
            }
            if (rowA + 8 < NN) {
                float2 u = *(const float2*)(g_t2 + (size_t)(rowA + 8) * DD + c);
                *(float2*)(g_t3 + (size_t)(rowA + 8) * DD + c) =
                    make_float2(acc[mt][j][2] + 0.5f * u.x,
                                acc[mt][j][3] + 0.5f * u.y);
            }
        }
    }
}

// ---------------- fused edge output kernel -------------------------------------
// ef2 = relu(ef @ M + t3[dst] + 0.5*t2[src] + db + eb)
__global__ __launch_bounds__(512, 1)
void edge_out_gemm(const float* __restrict__ ef, const int* __restrict__ src,
                   const int* __restrict__ dst, const float* __restrict__ db,
                   const float* __restrict__ eb, float* __restrict__ out) {
    extern __shared__ uint32_t sm[];
    const int tid = threadIdx.x, lane = tid & 31, wid = tid >> 5;
    const int e0 = blockIdx.x * 128;
    const int mbase = (wid & 3) * 32, nbase = (wid >> 2) * 32;
    const int g = lane >> 2, t = lane & 3;

    fillB(sm, g_Bm_h, g_Bm_l, tid);
#pragma unroll
    for (int i = 0; i < 16; i++) {
        int idx = tid + i * 512;
        int r = idx >> 6, w = idx & 63;
        float2 v = *(const float2*)(ef + (size_t)(e0 + r) * DD + 2 * w);
        split2(v.x, v.y, sm[SA_H + r * WPAD + w], sm[SA_L + r * WPAD + w]);
    }
    __syncthreads();

    float acc[2][4][4];
    zero_acc(acc);
    kloop(sm, lane, mbase, nbase, acc);

#pragma unroll
    for (int mt = 0; mt < 2; mt++) {
        int e = e0 + mbase + mt * 16 + g;
        int dnA = dst[e], snA = src[e];
        int dnB = dst[e + 8], snB = src[e + 8];
        const float* t3A = g_t3 + (size_t)dnA * DD;
        const float* t2A = g_t2 + (size_t)snA * DD;
        const float* t3B = g_t3 + (size_t)dnB * DD;
        const float* t2B = g_t2 + (size_t)snB * DD;
#pragma unroll
        for (int j = 0; j < 4; j++) {
            int c = nbase + j * 8 + 2 * t;
            float2 d1 = *(const float2*)(db + c);
            float2 d2 = *(const float2*)(eb + c);
            float bx = d1.x + d2.x, by = d1.y + d2.y;

            float2 p1 = *(const float2*)(t3A + c);
            float2 p2 = *(const float2*)(t2A + c);
            float2 oA;
            oA.x = fmaxf(acc[mt][j][0] + p1.x + 0.5f * p2.x + bx, 0.f);
            oA.y = fmaxf(acc[mt][j][1] + p1.y + 0.5f * p2.y + by, 0.f);
            *(float2*)(out + (size_t)e * DD + c) = oA;

            float2 q1 = *(const float2*)(t3B + c);
            float2 q2 = *(const float2*)(t2B + c);
            float2 oB;
            oB.x = fmaxf(acc[mt][j][2] + q1.x + 0.5f * q2.x + bx, 0.f);
            oB.y = fmaxf(acc[mt][j][3] + q1.y + 0.5f * q2.y + by, 0.f);
            *(float2*)(out + (size_t)(e + 8) * DD + c) = oB;
        }
    }
}

// ---------------- launch ------------------------------------------------------
extern "C" void kernel_launch(void* const* d_in, const int* in_sizes, int n_in,
                              void* d_out, int out_size) {
    (void)in_sizes; (void)n_in; (void)out_size;
    const float* nf        = (const float*)d_in[0];
    const float* ef        = (const float*)d_in[1];
    const float* W_node    = (const float*)d_in[2];
    const float* W_edge    = (const float*)d_in[3];
    const float* node_bias = (const float*)d_in[4];
    const float* edge_bias = (const float*)d_in[5];
    const float* dense_W   = (const float*)d_in[6];
    const float* dense_b   = (const float*)d_in[7];
    const int*   src       = (const int*)d_in[8];
    const int*   dst       = (const int*)d_in[9];

    float* nf2 = (float*)d_out;
    float* ef2 = (float*)d_out + (size_t)NN * DD;

    cudaFuncSetAttribute(scatter_ef, cudaFuncAttributeMaxDynamicSharedMemorySize, SCAT_SMEM);
    cudaFuncSetAttribute(node_pass_a, cudaFuncAttributeMaxDynamicSharedMemorySize, SMEM_BYTES);
    cudaFuncSetAttribute(node_pass_b, cudaFuncAttributeMaxDynamicSharedMemorySize, SMEM_BYTES);
    cudaFuncSetAttribute(edge_out_gemm, cudaFuncAttributeMaxDynamicSharedMemorySize, SMEM_BYTES);

    const int NBLK = (NN + 127) / 128;

    zero_kernel<<<1024, 256>>>();
    prep_weights<<<64, 256>>>(W_node, W_edge, dense_W);
    scatter_ef<<<NE / 128, 256, SCAT_SMEM>>>(ef, dst);
    node_pass_a<<<NBLK, 512, SMEM_BYTES>>>(nf, node_bias, nf2);
    node_pass_b<<<NBLK, 512, SMEM_BYTES>>>();
    edge_out_gemm<<<NE / 128, 512, SMEM_BYTES>>>(ef, src, dst, dense_b,
                                                 edge_bias, ef2);
}